// round 1
// baseline (speedup 1.0000x reference)
#include <cuda_runtime.h>

// ---------------------------------------------------------------------------
// GroupedQueryAttention, restructured:
//   x_embed is affine in scalar x[b,s]  =>  K[b,s,j] = x*kwf[j] + kc[s,j]
//   score[g,p,b,s] (log2 domain) = a[g,p]*x[b,s] + bconst[g,p,s]
//   attn = e / Z  (no max-subtract needed: |score*log2e| <~ 9, exp2-safe)
//   ctx  = invZ * ( sum_s e*vc[s,:] + (sum_s e*x) * vw )
//   out  = ctx @ o_w + o_b
// Pair index p in [0,32) per group g: r = p>>3, q = p&7, head h = g*4+r.
// ---------------------------------------------------------------------------

#define LOG2E_OVER_SCALE ((float)(1.4426950408889634 / 2.8284271247461903))

__device__ __align__(16) float g_bconst[2][32][1024];     // 256 KB
__device__ __align__(16) float g_vc2f[2][4][1024][2];     // 64 KB (vc as [g][jj][s]{lo,hi})
__device__ __align__(16) float g_kc[1024][16];            // 64 KB
__device__ float g_a[2][32];
__device__ float g_vw[2][8];
__device__ __align__(16) float g_ctx[1024][8][64];        // 2 MB scratch

__device__ __forceinline__ float ex2f(float x) {
    float r; asm("ex2.approx.ftz.f32 %0, %1;" : "=f"(r) : "f"(x)); return r;
}
__device__ __forceinline__ unsigned long long pack2(float a, float b) {
    unsigned long long r; asm("mov.b64 %0, {%1, %2};" : "=l"(r) : "f"(a), "f"(b)); return r;
}
__device__ __forceinline__ void unpack2(unsigned long long v, float& a, float& b) {
    asm("mov.b64 {%0, %1}, %2;" : "=f"(a), "=f"(b) : "l"(v));
}
__device__ __forceinline__ void fma2(unsigned long long& d, unsigned long long a, unsigned long long b) {
    asm("fma.rn.f32x2 %0, %1, %2, %0;" : "+l"(d) : "l"(a), "l"(b));
}
__device__ __forceinline__ float wsum(float v) {
#pragma unroll
    for (int m = 16; m > 0; m >>= 1) v += __shfl_xor_sync(0xffffffffu, v, m);
    return v;
}

// --- precompute 1: kwf -> a[g][p], vwf -> g_vw -------------------------------
__global__ void k_pre1(const float* __restrict__ fe_w, const float* __restrict__ k_w,
                       const float* __restrict__ v_w, const float* __restrict__ queries) {
    __shared__ float kw[16];
    int t = threadIdx.x;  // 64 threads
    if (t < 16) {
        float sk = 0.f, sv = 0.f;
        for (int d = 0; d < 64; d++) {
            sk = fmaf(fe_w[d], k_w[d * 16 + t], sk);
            sv = fmaf(fe_w[d], v_w[d * 16 + t], sv);
        }
        kw[t] = sk;
        g_vw[t >> 3][t & 7] = sv;
    }
    __syncthreads();
    int g = t >> 5, p = t & 31, r = p >> 3, q = p & 7, h = g * 4 + r;
    float s = 0.f;
#pragma unroll
    for (int j = 0; j < 8; j++) s = fmaf(queries[q * 64 + h * 8 + j], kw[g * 8 + j], s);
    g_a[g][p] = s * LOG2E_OVER_SCALE;
}

// --- precompute 2a: kc[s][j], vc tables --------------------------------------
__global__ void k_pre2a(const float* __restrict__ fe_b, const float* __restrict__ pos_emb,
                        const float* __restrict__ k_w, const float* __restrict__ k_b,
                        const float* __restrict__ v_w, const float* __restrict__ v_b) {
    int t = blockIdx.x * blockDim.x + threadIdx.x;  // 16384 threads
    int s = t >> 4, j = t & 15;
    float kc = k_b[j], vc = v_b[j];
    for (int d = 0; d < 64; d++) {
        float e = fe_b[d] + pos_emb[s * 64 + d];
        kc = fmaf(e, k_w[d * 16 + j], kc);
        vc = fmaf(e, v_w[d * 16 + j], vc);
    }
    g_kc[s][j] = kc;
    g_vc2f[j >> 3][(j & 7) >> 1][s][j & 1] = vc;
}

// --- precompute 2b: bconst[g][p][s] ------------------------------------------
__global__ void k_pre2b(const float* __restrict__ queries) {
    int t = blockIdx.x * blockDim.x + threadIdx.x;  // 65536 threads
    int s = t & 1023, pp = t >> 10;
    int g = pp >> 5, p = pp & 31, r = p >> 3, q = p & 7, h = g * 4 + r;
    float acc = 0.f;
#pragma unroll
    for (int j = 0; j < 8; j++) acc = fmaf(queries[q * 64 + h * 8 + j], g_kc[s][g * 8 + j], acc);
    g_bconst[g][p][s] = acc * LOG2E_OVER_SCALE;
}

// --- main: softmax + attn store + ctx ---------------------------------------
__global__ __launch_bounds__(512, 1) void k_main(const float* __restrict__ x,
                                                 float* __restrict__ attn_out) {
    extern __shared__ float smem[];
    float* sm_b = smem;                                                  // 32768 floats
    unsigned long long* sm_vcu = (unsigned long long*)(smem + 32768);    // 4096 u64
    float* sm_x = smem + 32768 + 8192;                                   // 1024 floats
    const int g = blockIdx.y;
    const int tid = threadIdx.x;

    {   // cache group tables in smem once per CTA
        const float4* src = (const float4*)&g_bconst[g][0][0];
        float4* dst = (float4*)sm_b;
#pragma unroll
        for (int i = 0; i < 16; i++) dst[tid + 512 * i] = src[tid + 512 * i];
        const float4* vs = (const float4*)&g_vc2f[g][0][0][0];
        float4* vd = (float4*)(smem + 32768);
#pragma unroll
        for (int i = 0; i < 4; i++) vd[tid + 512 * i] = vs[tid + 512 * i];
    }

    const int w = tid >> 5, lane = tid & 31;
    const int p0 = 2 * w, p1 = 2 * w + 1;
    const float a0 = g_a[g][p0], a1 = g_a[g][p1];
    const int h0 = g * 4 + (p0 >> 3), q0 = p0 & 7;
    const int h1 = g * 4 + (p1 >> 3), q1 = p1 & 7;
    float vw[8];
#pragma unroll
    for (int j = 0; j < 8; j++) vw[j] = g_vw[g][j];

    for (int b = blockIdx.x; b < 1024; b += 148) {
        __syncthreads();
        sm_x[tid] = x[b * 1024 + tid];
        sm_x[tid + 512] = x[b * 1024 + 512 + tid];
        __syncthreads();

        float eA[32], eB[32];
        float z0 = 0.f, z1 = 0.f, xs0 = 0.f, xs1 = 0.f;
        unsigned long long c0[4], c1[4];
#pragma unroll
        for (int k = 0; k < 4; k++) { c0[k] = 0ull; c1[k] = 0ull; }

#pragma unroll
        for (int i = 0; i < 32; i++) {
            int s = i * 32 + lane;
            float xv = sm_x[s];
            float e0 = ex2f(fmaf(a0, xv, sm_b[p0 * 1024 + s]));
            float e1 = ex2f(fmaf(a1, xv, sm_b[p1 * 1024 + s]));
            eA[i] = e0; eB[i] = e1;
            z0 += e0; z1 += e1;
            xs0 = fmaf(e0, xv, xs0); xs1 = fmaf(e1, xv, xs1);
            unsigned long long pe0 = pack2(e0, e0), pe1 = pack2(e1, e1);
#pragma unroll
            for (int k = 0; k < 4; k++) {
                unsigned long long vv = sm_vcu[k * 1024 + s];
                fma2(c0[k], pe0, vv);
                fma2(c1[k], pe1, vv);
            }
        }

        z0 = wsum(z0); z1 = wsum(z1); xs0 = wsum(xs0); xs1 = wsum(xs1);
        float cf0[8], cf1[8];
#pragma unroll
        for (int k = 0; k < 4; k++) {
            unpack2(c0[k], cf0[2 * k], cf0[2 * k + 1]);
            unpack2(c1[k], cf1[2 * k], cf1[2 * k + 1]);
        }
#pragma unroll
        for (int j = 0; j < 8; j++) { cf0[j] = wsum(cf0[j]); cf1[j] = wsum(cf1[j]); }

        float invZ0 = 1.0f / z0, invZ1 = 1.0f / z1;
        if (lane == 0) {
#pragma unroll
            for (int j = 0; j < 8; j++) {
                g_ctx[b][q0][h0 * 8 + j] = invZ0 * fmaf(xs0, vw[j], cf0[j]);
                g_ctx[b][q1][h1 * 8 + j] = invZ1 * fmaf(xs1, vw[j], cf1[j]);
            }
        }

        float* o0 = attn_out + (((size_t)b * 8 + h0) * 8 + q0) * 1024 + lane;
        float* o1 = attn_out + (((size_t)b * 8 + h1) * 8 + q1) * 1024 + lane;
#pragma unroll
        for (int i = 0; i < 32; i++) {
            o0[i * 32] = eA[i] * invZ0;
            o1[i * 32] = eB[i] * invZ1;
        }
    }
}

// --- epilogue: out = ctx @ o_w + o_b -----------------------------------------
__global__ __launch_bounds__(512) void k_epilogue(const float* __restrict__ o_w,
                                                  const float* __restrict__ o_b,
                                                  float* __restrict__ out) {
    __shared__ float sc[512];
    int b = blockIdx.x, t = threadIdx.x;
    sc[t] = ((const float*)g_ctx)[b * 512 + t];
    __syncthreads();
    int q = t >> 6, e = t & 63;
    float acc = o_b[e];
#pragma unroll
    for (int f = 0; f < 64; f++) acc = fmaf(sc[q * 64 + f], o_w[f * 64 + e], acc);
    out[(size_t)b * 512 + t] = acc;
}

// ---------------------------------------------------------------------------
extern "C" void kernel_launch(void* const* d_in, const int* in_sizes, int n_in,
                              void* d_out, int out_size) {
    const float* x       = (const float*)d_in[0];
    const float* queries = (const float*)d_in[1];
    const float* fe_w    = (const float*)d_in[2];
    const float* fe_b    = (const float*)d_in[3];
    const float* pos_emb = (const float*)d_in[4];
    const float* k_w     = (const float*)d_in[5];
    const float* k_b     = (const float*)d_in[6];
    const float* v_w     = (const float*)d_in[7];
    const float* v_b     = (const float*)d_in[8];
    const float* o_w     = (const float*)d_in[9];
    const float* o_b     = (const float*)d_in[10];

    float* out  = (float*)d_out;                 // [1024, 512]
    float* attn = out + 1024 * 512;              // [1024, 8, 8, 1024]

    int smem_bytes = (32768 + 8192 + 1024) * 4;  // 167,936 B
    cudaFuncSetAttribute(k_main, cudaFuncAttributeMaxDynamicSharedMemorySize, smem_bytes);

    k_pre1<<<1, 64>>>(fe_w, k_w, v_w, queries);
    k_pre2a<<<128, 128>>>(fe_b, pos_emb, k_w, k_b, v_w, v_b);
    k_pre2b<<<256, 256>>>(queries);
    k_main<<<dim3(148, 2), 512, smem_bytes>>>(x, attn);
    k_epilogue<<<1024, 512>>>(o_w, o_b, out);
}